// round 9
// baseline (speedup 1.0000x reference)
#include <cuda_runtime.h>

#define FEAT 64

// Scratch buffers (static __device__ — no allocation allowed).
#define NMAX 100000
#define EMAX 1600000
__device__ float4 g_bufA[(size_t)NMAX * (FEAT / 4)];
__device__ float4 g_bufB[(size_t)NMAX * (FEAT / 4)];
__device__ int    g_rowptr[NMAX + 1];
__device__ int    g_cursor[NMAX];      // doubles as degree histogram
__device__ int    g_adj[EMAX];
__device__ int    g_bsum[1024];

// ---------------------------------------------------------------------------
__global__ void zero_kernel(float* __restrict__ p, int n) {
    int i = blockIdx.x * blockDim.x + threadIdx.x;
    if (i < n) p[i] = 0.0f;
}
__global__ void zero_int_kernel(int* __restrict__ p, int n) {
    int i = blockIdx.x * blockDim.x + threadIdx.x;
    if (i < n) p[i] = 0;
}

// ---------------------------------------------------------------------------
// CSR build: histogram -> scan -> fill
// ---------------------------------------------------------------------------
__global__ void hist_kernel(int* __restrict__ deg, const int* __restrict__ ei, int E) {
    int e = blockIdx.x * blockDim.x + threadIdx.x;
    if (e < E) atomicAdd(&deg[ei[(size_t)E + e]], 1);
}

__global__ void scan1_kernel(const int* __restrict__ deg, int* __restrict__ rowptr,
                             int* __restrict__ bsum, int Nn) {
    __shared__ int sm[256];
    int i = blockIdx.x * 256 + threadIdx.x;
    int v = (i < Nn) ? deg[i] : 0;
    sm[threadIdx.x] = v;
    __syncthreads();
    for (int off = 1; off < 256; off <<= 1) {
        int t = (threadIdx.x >= off) ? sm[threadIdx.x - off] : 0;
        __syncthreads();
        sm[threadIdx.x] += t;
        __syncthreads();
    }
    if (i < Nn) rowptr[i] = sm[threadIdx.x] - v;
    if (threadIdx.x == 255) bsum[blockIdx.x] = sm[255];
}

__global__ void scan3_kernel(int* __restrict__ rowptr, int* __restrict__ cursor,
                             const int* __restrict__ bsum, int Nn, int E) {
    __shared__ int sred[256];
    int t = threadIdx.x;
    int partial = 0;
    for (int j = t; j < blockIdx.x; j += 256) partial += bsum[j];
    sred[t] = partial;
    __syncthreads();
    for (int off = 128; off > 0; off >>= 1) {
        if (t < off) sred[t] += sred[t + off];
        __syncthreads();
    }
    int blockOff = sred[0];
    int i = blockIdx.x * 256 + t;
    if (i < Nn) {
        int v = rowptr[i] + blockOff;
        rowptr[i] = v;
        cursor[i] = v;
    }
    if (i == 0) rowptr[Nn] = E;
}

__global__ void fill_kernel(int* __restrict__ adj, int* __restrict__ cursor,
                            const int* __restrict__ ei, int E) {
    int e = blockIdx.x * blockDim.x + threadIdx.x;
    if (e < E) {
        int s = ei[e];
        int d = ei[(size_t)E + e];
        int p = atomicAdd(&cursor[d], 1);
        adj[p] = s;
    }
}

// ---------------------------------------------------------------------------
// Fused GIN layer: Y = sigmoid(sigmoid((h + sum_neigh h) @ W1) @ W2)
//   512 threads/block, 128 rows/block.
//   GEMM mapping: warp w -> cols 4w..4w+3 (W loads warp-uniform = LDS
//   broadcast, ~zero crossbar cost); lane t -> rows {t,t+32,t+64,t+96}
//   (conflict-free X loads, stride 66). FMA2 paired over (k,k+1); W staged
//   transposed [c][k] so w k-pairs are contiguous.
// ---------------------------------------------------------------------------
#define SXS 66
#define SW_FLOATS (64 * SXS)       // 4224 floats per W (transposed, stride 66)
#define SX_FLOATS (128 * SXS)      // 8448
#define LAYER_SMEM_BYTES ((2 * SW_FLOATS + SX_FLOATS) * 4)   // 67.6 KB

// stage W transposed: sWT[c*66 + k] = W[k][c]
__device__ __forceinline__ void stage_wt_tr(float* sWT, const float4* W4, int tid) {
#pragma unroll
    for (int it = 0; it < 2; it++) {
        int idx = tid + it * 512;      // 0..1023
        int k   = idx >> 4;
        int c4  = idx & 15;
        float4 v = W4[idx];            // W[k][4c4 .. 4c4+3]
        int c = c4 * 4;
        sWT[(c + 0) * SXS + k] = v.x;
        sWT[(c + 1) * SXS + k] = v.y;
        sWT[(c + 2) * SXS + k] = v.z;
        sWT[(c + 3) * SXS + k] = v.w;
    }
}

// 4 rows (t + 32i) x 4 cols (4w..4w+3); acc paired over (k,k+1).
// xb = sX + t (row base given lane), wb = sWT + 4w*SXS (warp-uniform)
__device__ __forceinline__ void mlp_bc(const float* __restrict__ sX, int t,
                                       const float* __restrict__ wb,
                                       float o[4][4]) {
    unsigned long long acc[4][4];
#pragma unroll
    for (int c = 0; c < 4; c++)
#pragma unroll
        for (int i = 0; i < 4; i++) acc[c][i] = 0ull;

#pragma unroll 4
    for (int k = 0; k < 64; k += 2) {
        unsigned long long xv[4], wv[4];
#pragma unroll
        for (int i = 0; i < 4; i++)
            xv[i] = *(const unsigned long long*)(sX + (t + 32 * i) * SXS + k);
#pragma unroll
        for (int c = 0; c < 4; c++)
            wv[c] = *(const unsigned long long*)(wb + c * SXS + k);  // uniform
#pragma unroll
        for (int i = 0; i < 4; i++)
#pragma unroll
            for (int c = 0; c < 4; c++)
                asm("fma.rn.f32x2 %0, %1, %2, %0;"
                    : "+l"(acc[c][i]) : "l"(xv[i]), "l"(wv[c]));
    }
#pragma unroll
    for (int i = 0; i < 4; i++)
#pragma unroll
        for (int c = 0; c < 4; c++) {
            float lo, hi;
            asm("mov.b64 {%0, %1}, %2;" : "=f"(lo), "=f"(hi) : "l"(acc[c][i]));
            float v = lo + hi;
            o[i][c] = 1.0f / (1.0f + __expf(-v));
        }
}

__global__ __launch_bounds__(512, 2) void layer_kernel(
    float* __restrict__ Y, const float* __restrict__ H,
    const int* __restrict__ rowptr, const int* __restrict__ adj,
    const float* __restrict__ W1, const float* __restrict__ W2,
    float* __restrict__ xr, const int* __restrict__ batch, int Nn)
{
    extern __shared__ float sm[];
    float* sW1T = sm;
    float* sW2T = sm + SW_FLOATS;
    float* sX   = sm + 2 * SW_FLOATS;
    int tid  = threadIdx.x;
    int row0 = blockIdx.x * 128;

    stage_wt_tr(sW1T, (const float4*)W1, tid);
    stage_wt_tr(sW2T, (const float4*)W2, tid);

    // ---- phase 0: gather 128 rows (half-warp per node, 32 nodes/pass) ----
    {
        int lane = tid & 31;
        int half = lane & 16;
        unsigned hmask = half ? 0xffff0000u : 0x0000ffffu;
        int t  = lane & 15;
        int hw = tid >> 4;               // 0..31
        const float4* H4 = (const float4*)H;
#pragma unroll
        for (int pass = 0; pass < 4; pass++) {
            int r = pass * 32 + hw;      // local row 0..127
            int n = row0 + r;
            bool valid = (n < Nn);
            int n_cl = valid ? n : (Nn - 1);
            int start = rowptr[n_cl];
            int end   = rowptr[n_cl + 1];
            float4 acc = H4[(size_t)n_cl * 16 + t];
            int base = start;
            for (; base + 16 <= end; base += 16) {
                int idx = adj[base + t];
                float4 v[8];
#pragma unroll
                for (int j = 0; j < 8; j++) {
                    int s = __shfl_sync(hmask, idx, half + j);
                    v[j] = H4[(size_t)s * 16 + t];
                }
#pragma unroll
                for (int j = 0; j < 8; j++) {
                    acc.x += v[j].x; acc.y += v[j].y; acc.z += v[j].z; acc.w += v[j].w;
                }
#pragma unroll
                for (int j = 0; j < 8; j++) {
                    int s = __shfl_sync(hmask, idx, half + 8 + j);
                    v[j] = H4[(size_t)s * 16 + t];
                }
#pragma unroll
                for (int j = 0; j < 8; j++) {
                    acc.x += v[j].x; acc.y += v[j].y; acc.z += v[j].z; acc.w += v[j].w;
                }
            }
            int rem = end - base;
            if (rem > 0) {
                int idx = (t < rem) ? adj[base + t] : 0;
                for (int j = 0; j < rem; j++) {
                    int s = __shfl_sync(hmask, idx, half + j);
                    float4 v = H4[(size_t)s * 16 + t];
                    acc.x += v.x; acc.y += v.y; acc.z += v.z; acc.w += v.w;
                }
            }
            // STS.64 pairs (16B alignment not guaranteed at stride 66)
            float* dp = &sX[r * SXS + t * 4];
            ((float2*)dp)[0] = make_float2(acc.x, acc.y);
            ((float2*)dp)[1] = make_float2(acc.z, acc.w);
        }
    }
    __syncthreads();

    int w = tid >> 5;        // warp 0..15 -> cols 4w..4w+3
    int t = tid & 31;        // lane -> rows {t, t+32, t+64, t+96}
    const float* wb1 = sW1T + w * 4 * SXS;
    const float* wb2 = sW2T + w * 4 * SXS;
    float o[4][4];

    // ---- phase 1: H1 = sigmoid(X @ W1), written back into sX ----
    mlp_bc(sX, t, wb1, o);
    __syncthreads();        // all reads of sX complete
#pragma unroll
    for (int i = 0; i < 4; i++) {
        float* dp = &sX[(t + 32 * i) * SXS + w * 4];
        ((float2*)dp)[0] = make_float2(o[i][0], o[i][1]);
        ((float2*)dp)[1] = make_float2(o[i][2], o[i][3]);
    }
    __syncthreads();

    // ---- phase 2: Y = sigmoid(H1 @ W2) ----
    mlp_bc(sX, t, wb2, o);
    int cbase = w * 4;
    if (xr == nullptr) {
#pragma unroll
        for (int i = 0; i < 4; i++) {
            int row = row0 + t + 32 * i;
            if (row < Nn)
                *(float4*)(Y + (size_t)row * 64 + cbase) =
                    make_float4(o[i][0], o[i][1], o[i][2], o[i][3]);
        }
    } else {
        // final layer: pool fused — RED into xr[batch[row]]
#pragma unroll
        for (int i = 0; i < 4; i++) {
            int row = row0 + t + 32 * i;
            if (row < Nn) {
                int g = batch[row];
                float* p = xr + (size_t)g * 64 + cbase;
                asm volatile("red.global.add.v4.f32 [%0], {%1, %2, %3, %4};"
                             :: "l"(p), "f"(o[i][0]), "f"(o[i][1]),
                                "f"(o[i][2]), "f"(o[i][3])
                             : "memory");
            }
        }
    }
}

// ---------------------------------------------------------------------------
// head: logits = xr @ fc_w^T + fc_b ; out = log_softmax(logits)
// ---------------------------------------------------------------------------
__global__ void head_kernel(float* __restrict__ out, const float* __restrict__ xr,
                            const float* __restrict__ fc_w, const float* __restrict__ fc_b,
                            int C, int B) {
    int g = blockIdx.x * blockDim.x + threadIdx.x;
    if (g >= B) return;
    float xv[FEAT];
#pragma unroll
    for (int i = 0; i < FEAT; i++) xv[i] = xr[(size_t)g * FEAT + i];
    float lg[16];
    float m = -1e30f;
    for (int c = 0; c < C; c++) {
        float s = fc_b[c];
#pragma unroll
        for (int i = 0; i < FEAT; i++) s += xv[i] * fc_w[(size_t)c * FEAT + i];
        lg[c] = s;
        m = fmaxf(m, s);
    }
    float sum = 0.0f;
    for (int c = 0; c < C; c++) sum += expf(lg[c] - m);
    float lse = m + logf(sum);
    for (int c = 0; c < C; c++) out[(size_t)g * C + c] = lg[c] - lse;
}

// ---------------------------------------------------------------------------
extern "C" void kernel_launch(void* const* d_in, const int* in_sizes, int n_in,
                              void* d_out, int out_size) {
    const float* x     = (const float*)d_in[0];
    const int*   ei    = (const int*)d_in[1];    // int64 narrowed to int32 by harness
    const int*   batch = (const int*)d_in[2];
    const float* W1s   = (const float*)d_in[3];
    const float* W2s   = (const float*)d_in[4];
    const float* fc_w  = (const float*)d_in[5];
    const float* fc_b  = (const float*)d_in[6];

    int Nn = in_sizes[0] / FEAT;           // 100000
    int E  = in_sizes[1] / 2;              // 1600000
    int C  = in_sizes[6];                  // 10
    int L  = in_sizes[3] / (FEAT * FEAT);  // 4
    int B  = out_size / (C + FEAT);        // 128

    static int smem_set = 0;
    if (!smem_set) {
        cudaFuncSetAttribute(layer_kernel,
                             cudaFuncAttributeMaxDynamicSharedMemorySize,
                             LAYER_SMEM_BYTES);
        smem_set = 1;
    }

    float4 *bufA4, *bufB4;
    int *rowptr, *cursor, *adj, *bsum;
    cudaGetSymbolAddress((void**)&bufA4, g_bufA);
    cudaGetSymbolAddress((void**)&bufB4, g_bufB);
    cudaGetSymbolAddress((void**)&rowptr, g_rowptr);
    cudaGetSymbolAddress((void**)&cursor, g_cursor);
    cudaGetSymbolAddress((void**)&adj, g_adj);
    cudaGetSymbolAddress((void**)&bsum, g_bsum);
    float* A  = (float*)bufA4;
    float* Bv = (float*)bufB4;

    int nb        = (Nn + 255) / 256;
    int eBlocks   = (E + 255) / 256;
    int layerBlks = (Nn + 127) / 128;

    float* out = (float*)d_out;
    float* xr  = out + (size_t)B * C;

    // ---- CSR build (once per launch) ----
    zero_int_kernel<<<nb, 256>>>(cursor, Nn);
    hist_kernel<<<eBlocks, 256>>>(cursor, ei, E);
    scan1_kernel<<<nb, 256>>>(cursor, rowptr, bsum, Nn);
    scan3_kernel<<<nb, 256>>>(rowptr, cursor, bsum, Nn, E);
    fill_kernel<<<eBlocks, 256>>>(adj, cursor, ei, E);

    // zero output (xr is RED target of the final fused layer)
    zero_kernel<<<(out_size + 255) / 256, 256>>>(out, out_size);

    // ---- layers (ping-pong; final layer REDs into xr instead of writing H) ----
    const float* H = x;
    float* Y = A;
    for (int l = 0; l < L; l++) {
        bool last = (l == L - 1);
        layer_kernel<<<layerBlks, 512, LAYER_SMEM_BYTES>>>(
            Y, H, rowptr, adj,
            W1s + (size_t)l * FEAT * FEAT, W2s + (size_t)l * FEAT * FEAT,
            last ? xr : nullptr, batch, Nn);
        H = Y;
        Y = (Y == A) ? Bv : A;
    }

    head_kernel<<<(B + 127) / 128, 128>>>(out, xr, fc_w, fc_b, C, B);
}

// round 10
// speedup vs baseline: 1.1238x; 1.1238x over previous
#include <cuda_runtime.h>

#define FEAT 64

// Scratch buffers (static __device__ — no allocation allowed).
#define NMAX 100000
#define EMAX 1600000
__device__ float4 g_bufA[(size_t)NMAX * (FEAT / 4)];
__device__ float4 g_bufB[(size_t)NMAX * (FEAT / 4)];
__device__ int    g_rowptr[NMAX + 1];
__device__ int    g_cursor[NMAX];      // doubles as degree histogram
__device__ int    g_adj[EMAX];
__device__ int    g_bsum[1024];

// ---------------------------------------------------------------------------
// merged zero: out[0..nOut) = 0.f and cursor[0..nInt) = 0
// (single kernel so the pre-layer launch count is 5 and ncu -s 5 captures
//  layer_kernel)
// ---------------------------------------------------------------------------
__global__ void zero_both_kernel(float* __restrict__ out, int nOut,
                                 int* __restrict__ cursor, int nInt) {
    int i = blockIdx.x * blockDim.x + threadIdx.x;
    if (i < nOut) out[i] = 0.0f;
    if (i < nInt) cursor[i] = 0;
}

// ---------------------------------------------------------------------------
// CSR build: histogram -> scan -> fill
// ---------------------------------------------------------------------------
__global__ void hist_kernel(int* __restrict__ deg, const int* __restrict__ ei, int E) {
    int e = blockIdx.x * blockDim.x + threadIdx.x;
    if (e < E) atomicAdd(&deg[ei[(size_t)E + e]], 1);
}

__global__ void scan1_kernel(const int* __restrict__ deg, int* __restrict__ rowptr,
                             int* __restrict__ bsum, int Nn) {
    __shared__ int sm[256];
    int i = blockIdx.x * 256 + threadIdx.x;
    int v = (i < Nn) ? deg[i] : 0;
    sm[threadIdx.x] = v;
    __syncthreads();
    for (int off = 1; off < 256; off <<= 1) {
        int t = (threadIdx.x >= off) ? sm[threadIdx.x - off] : 0;
        __syncthreads();
        sm[threadIdx.x] += t;
        __syncthreads();
    }
    if (i < Nn) rowptr[i] = sm[threadIdx.x] - v;
    if (threadIdx.x == 255) bsum[blockIdx.x] = sm[255];
}

__global__ void scan3_kernel(int* __restrict__ rowptr, int* __restrict__ cursor,
                             const int* __restrict__ bsum, int Nn, int E) {
    __shared__ int sred[256];
    int t = threadIdx.x;
    int partial = 0;
    for (int j = t; j < blockIdx.x; j += 256) partial += bsum[j];
    sred[t] = partial;
    __syncthreads();
    for (int off = 128; off > 0; off >>= 1) {
        if (t < off) sred[t] += sred[t + off];
        __syncthreads();
    }
    int blockOff = sred[0];
    int i = blockIdx.x * 256 + t;
    if (i < Nn) {
        int v = rowptr[i] + blockOff;
        rowptr[i] = v;
        cursor[i] = v;
    }
    if (i == 0) rowptr[Nn] = E;
}

__global__ void fill_kernel(int* __restrict__ adj, int* __restrict__ cursor,
                            const int* __restrict__ ei, int E) {
    int e = blockIdx.x * blockDim.x + threadIdx.x;
    if (e < E) {
        int s = ei[e];
        int d = ei[(size_t)E + e];
        int p = atomicAdd(&cursor[d], 1);
        adj[p] = s;
    }
}

// ---------------------------------------------------------------------------
// Fused GIN layer: Y = sigmoid(sigmoid((h + sum_neigh h) @ W1) @ W2)
//   512 threads/block, 128 rows/block.
//   Phase 0: gather (half-warp per node) -> sX
//   Phase 1: H1 = sigmoid(sX @ W1) -> back into sX (aliased)
//   Phase 2: Y  = sigmoid(sX @ W2) -> global  (or RED into xr[batch] if xr!=0)
//   GEMM mapping (bank-verified): tr = tid>>4 (rows, X loads broadcast per
//   16 lanes), tc = tid&15 (cols, W loads 16 distinct even banks via skew).
// ---------------------------------------------------------------------------
#define SXS 66
#define SWS 66
#define SW_FLOATS 4240
#define SX_FLOATS 8448
#define LAYER_SMEM_BYTES ((2 * SW_FLOATS + SX_FLOATS) * 4)

__device__ __forceinline__ void stage_wt512(float* sWT, const float4* W4, int tid) {
#pragma unroll
    for (int it = 0; it < 2; it++) {
        int idx = tid + it * 512;      // 0..1023
        int k   = idx >> 4;
        int c4  = idx & 15;
        float4 v = W4[idx];
        int c = c4 * 4;
        sWT[(c + 0) * SWS + (((c + 0) >> 4) & 3) * 2 + k] = v.x;
        sWT[(c + 1) * SWS + (((c + 1) >> 4) & 3) * 2 + k] = v.y;
        sWT[(c + 2) * SWS + (((c + 2) >> 4) & 3) * 2 + k] = v.z;
        sWT[(c + 3) * SWS + (((c + 3) >> 4) & 3) * 2 + k] = v.w;
    }
}

// 4 rows x 4 cols per thread, FMA2 paired over (k, k+1)
__device__ __forceinline__ void mlp4(const float* __restrict__ xb,
                                     const float* __restrict__ wb,
                                     float o[4][4]) {
    unsigned long long acc[4][4];
#pragma unroll
    for (int c = 0; c < 4; c++)
#pragma unroll
        for (int i = 0; i < 4; i++) acc[c][i] = 0ull;

#pragma unroll 4
    for (int k = 0; k < 64; k += 2) {
        unsigned long long xv[4], wv[4];
#pragma unroll
        for (int i = 0; i < 4; i++)
            xv[i] = *(const unsigned long long*)(xb + i * SXS + k);
#pragma unroll
        for (int c = 0; c < 4; c++)
            wv[c] = *(const unsigned long long*)(wb + c * SWS + k);
#pragma unroll
        for (int i = 0; i < 4; i++)
#pragma unroll
            for (int c = 0; c < 4; c++)
                asm("fma.rn.f32x2 %0, %1, %2, %0;"
                    : "+l"(acc[c][i]) : "l"(xv[i]), "l"(wv[c]));
    }
#pragma unroll
    for (int i = 0; i < 4; i++)
#pragma unroll
        for (int c = 0; c < 4; c++) {
            float lo, hi;
            asm("mov.b64 {%0, %1}, %2;" : "=f"(lo), "=f"(hi) : "l"(acc[c][i]));
            float v = lo + hi;
            o[i][c] = 1.0f / (1.0f + __expf(-v));
        }
}

__global__ __launch_bounds__(512, 2) void layer_kernel(
    float* __restrict__ Y, const float* __restrict__ H,
    const int* __restrict__ rowptr, const int* __restrict__ adj,
    const float* __restrict__ W1, const float* __restrict__ W2,
    float* __restrict__ xr, const int* __restrict__ batch, int Nn)
{
    extern __shared__ float sm[];
    float* sW1T = sm;
    float* sW2T = sm + SW_FLOATS;
    float* sX   = sm + 2 * SW_FLOATS;
    int tid  = threadIdx.x;
    int row0 = blockIdx.x * 128;

    stage_wt512(sW1T, (const float4*)W1, tid);
    stage_wt512(sW2T, (const float4*)W2, tid);

    // ---- phase 0: gather 128 rows (half-warp per node, 32 nodes/pass) ----
    {
        int lane = tid & 31;
        int half = lane & 16;
        unsigned hmask = half ? 0xffff0000u : 0x0000ffffu;
        int t  = lane & 15;
        int hw = tid >> 4;               // 0..31
        const float4* H4 = (const float4*)H;
#pragma unroll
        for (int pass = 0; pass < 4; pass++) {
            int r = pass * 32 + hw;      // local row 0..127
            int n = row0 + r;
            bool valid = (n < Nn);
            int n_cl = valid ? n : (Nn - 1);
            int start = rowptr[n_cl];
            int end   = rowptr[n_cl + 1];
            float4 acc = H4[(size_t)n_cl * 16 + t];
            int base = start;
            for (; base + 16 <= end; base += 16) {
                int idx = adj[base + t];
                float4 v[8];
#pragma unroll
                for (int j = 0; j < 8; j++) {
                    int s = __shfl_sync(hmask, idx, half + j);
                    v[j] = H4[(size_t)s * 16 + t];
                }
#pragma unroll
                for (int j = 0; j < 8; j++) {
                    acc.x += v[j].x; acc.y += v[j].y; acc.z += v[j].z; acc.w += v[j].w;
                }
#pragma unroll
                for (int j = 0; j < 8; j++) {
                    int s = __shfl_sync(hmask, idx, half + 8 + j);
                    v[j] = H4[(size_t)s * 16 + t];
                }
#pragma unroll
                for (int j = 0; j < 8; j++) {
                    acc.x += v[j].x; acc.y += v[j].y; acc.z += v[j].z; acc.w += v[j].w;
                }
            }
            int rem = end - base;
            if (rem > 0) {
                int idx = (t < rem) ? adj[base + t] : 0;
                for (int j = 0; j < rem; j++) {
                    int s = __shfl_sync(hmask, idx, half + j);
                    float4 v = H4[(size_t)s * 16 + t];
                    acc.x += v.x; acc.y += v.y; acc.z += v.z; acc.w += v.w;
                }
            }
            float* dp = &sX[r * SXS + t * 4];
            ((float2*)dp)[0] = make_float2(acc.x, acc.y);
            ((float2*)dp)[1] = make_float2(acc.z, acc.w);
        }
    }
    __syncthreads();

    int tr = tid >> 4;      // 0..31 -> rows tr*4 .. tr*4+3
    int tc = tid & 15;      // 0..15 -> cols tc*4 .. tc*4+3
    int skew = ((tc >> 2) & 3) * 2;
    float o[4][4];

    // ---- phase 1: H1 = sigmoid(X @ W1), written back into sX ----
    mlp4(sX + tr * 4 * SXS, sW1T + tc * 4 * SWS + skew, o);
    __syncthreads();        // all reads of sX complete
#pragma unroll
    for (int i = 0; i < 4; i++) {
        float* dp = &sX[(tr * 4 + i) * SXS + tc * 4];
        ((float2*)dp)[0] = make_float2(o[i][0], o[i][1]);
        ((float2*)dp)[1] = make_float2(o[i][2], o[i][3]);
    }
    __syncthreads();

    // ---- phase 2: Y = sigmoid(H1 @ W2) ----
    mlp4(sX + tr * 4 * SXS, sW2T + tc * 4 * SWS + skew, o);
    int cbase = tc * 4;
    if (xr == nullptr) {
#pragma unroll
        for (int i = 0; i < 4; i++) {
            int row = row0 + tr * 4 + i;
            if (row < Nn)
                *(float4*)(Y + (size_t)row * 64 + cbase) =
                    make_float4(o[i][0], o[i][1], o[i][2], o[i][3]);
        }
    } else {
        // final layer: pool fused — RED into xr[batch[row]]
#pragma unroll
        for (int i = 0; i < 4; i++) {
            int row = row0 + tr * 4 + i;
            if (row < Nn) {
                int g = batch[row];
                float* p = xr + (size_t)g * 64 + cbase;
                asm volatile("red.global.add.v4.f32 [%0], {%1, %2, %3, %4};"
                             :: "l"(p), "f"(o[i][0]), "f"(o[i][1]),
                                "f"(o[i][2]), "f"(o[i][3])
                             : "memory");
            }
        }
    }
}

// ---------------------------------------------------------------------------
// head: logits = xr @ fc_w^T + fc_b ; out = log_softmax(logits)
// ---------------------------------------------------------------------------
__global__ void head_kernel(float* __restrict__ out, const float* __restrict__ xr,
                            const float* __restrict__ fc_w, const float* __restrict__ fc_b,
                            int C, int B) {
    int g = blockIdx.x * blockDim.x + threadIdx.x;
    if (g >= B) return;
    float xv[FEAT];
#pragma unroll
    for (int i = 0; i < FEAT; i++) xv[i] = xr[(size_t)g * FEAT + i];
    float lg[16];
    float m = -1e30f;
    for (int c = 0; c < C; c++) {
        float s = fc_b[c];
#pragma unroll
        for (int i = 0; i < FEAT; i++) s += xv[i] * fc_w[(size_t)c * FEAT + i];
        lg[c] = s;
        m = fmaxf(m, s);
    }
    float sum = 0.0f;
    for (int c = 0; c < C; c++) sum += expf(lg[c] - m);
    float lse = m + logf(sum);
    for (int c = 0; c < C; c++) out[(size_t)g * C + c] = lg[c] - lse;
}

// ---------------------------------------------------------------------------
extern "C" void kernel_launch(void* const* d_in, const int* in_sizes, int n_in,
                              void* d_out, int out_size) {
    const float* x     = (const float*)d_in[0];
    const int*   ei    = (const int*)d_in[1];    // int64 narrowed to int32 by harness
    const int*   batch = (const int*)d_in[2];
    const float* W1s   = (const float*)d_in[3];
    const float* W2s   = (const float*)d_in[4];
    const float* fc_w  = (const float*)d_in[5];
    const float* fc_b  = (const float*)d_in[6];

    int Nn = in_sizes[0] / FEAT;           // 100000
    int E  = in_sizes[1] / 2;              // 1600000
    int C  = in_sizes[6];                  // 10
    int L  = in_sizes[3] / (FEAT * FEAT);  // 4
    int B  = out_size / (C + FEAT);        // 128

    static int smem_set = 0;
    if (!smem_set) {
        cudaFuncSetAttribute(layer_kernel,
                             cudaFuncAttributeMaxDynamicSharedMemorySize,
                             LAYER_SMEM_BYTES);
        smem_set = 1;
    }

    float4 *bufA4, *bufB4;
    int *rowptr, *cursor, *adj, *bsum;
    cudaGetSymbolAddress((void**)&bufA4, g_bufA);
    cudaGetSymbolAddress((void**)&bufB4, g_bufB);
    cudaGetSymbolAddress((void**)&rowptr, g_rowptr);
    cudaGetSymbolAddress((void**)&cursor, g_cursor);
    cudaGetSymbolAddress((void**)&adj, g_adj);
    cudaGetSymbolAddress((void**)&bsum, g_bsum);
    float* A  = (float*)bufA4;
    float* Bv = (float*)bufB4;

    int nb        = (Nn + 255) / 256;
    int eBlocks   = (E + 255) / 256;
    int layerBlks = (Nn + 127) / 128;

    float* out = (float*)d_out;
    float* xr  = out + (size_t)B * C;

    // ---- CSR build + output zeroing (5 launches; layer0 is launch #6,
    //      which is what ncu -s 5 -c 1 captures) ----
    zero_both_kernel<<<nb, 256>>>(out, out_size, cursor, Nn);
    hist_kernel<<<eBlocks, 256>>>(cursor, ei, E);
    scan1_kernel<<<nb, 256>>>(cursor, rowptr, bsum, Nn);
    scan3_kernel<<<nb, 256>>>(rowptr, cursor, bsum, Nn, E);
    fill_kernel<<<eBlocks, 256>>>(adj, cursor, ei, E);

    // ---- layers (ping-pong; final layer REDs into xr instead of writing H) ----
    const float* H = x;
    float* Y = A;
    for (int l = 0; l < L; l++) {
        bool last = (l == L - 1);
        layer_kernel<<<layerBlks, 512, LAYER_SMEM_BYTES>>>(
            Y, H, rowptr, adj,
            W1s + (size_t)l * FEAT * FEAT, W2s + (size_t)l * FEAT * FEAT,
            last ? xr : nullptr, batch, Nn);
        H = Y;
        Y = (Y == A) ? Bv : A;
    }

    head_kernel<<<(B + 127) / 128, 128>>>(out, xr, fc_w, fc_b, C, B);
}

// round 14
// speedup vs baseline: 1.1874x; 1.0566x over previous
#include <cuda_runtime.h>

#define FEAT 64

// Scratch buffers (static __device__ — no allocation allowed).
#define NMAX 100000
#define EMAX 1600000
__device__ float4 g_bufA[(size_t)NMAX * (FEAT / 4)];
__device__ float4 g_bufB[(size_t)NMAX * (FEAT / 4)];
__device__ int    g_rowptr[NMAX + 1];
__device__ int    g_cursor[NMAX];
__device__ int    g_adj[EMAX];
__device__ int    g_bsum[1024];

// ---------------------------------------------------------------------------
__global__ void zero_both_kernel(float* __restrict__ out, int nOut,
                                 int* __restrict__ cursor, int nInt) {
    int i = blockIdx.x * blockDim.x + threadIdx.x;
    if (i < nOut) out[i] = 0.0f;
    if (i < nInt) cursor[i] = 0;
}

// ---------------------------------------------------------------------------
// CSR build: histogram -> scan -> fill
// ---------------------------------------------------------------------------
__global__ void hist_kernel(int* __restrict__ deg, const int* __restrict__ ei, int E) {
    int e = blockIdx.x * blockDim.x + threadIdx.x;
    if (e < E) atomicAdd(&deg[ei[(size_t)E + e]], 1);
}

__global__ void scan1_kernel(const int* __restrict__ deg, int* __restrict__ rowptr,
                             int* __restrict__ bsum, int Nn) {
    __shared__ int sm[256];
    int i = blockIdx.x * 256 + threadIdx.x;
    int v = (i < Nn) ? deg[i] : 0;
    sm[threadIdx.x] = v;
    __syncthreads();
    for (int off = 1; off < 256; off <<= 1) {
        int t = (threadIdx.x >= off) ? sm[threadIdx.x - off] : 0;
        __syncthreads();
        sm[threadIdx.x] += t;
        __syncthreads();
    }
    if (i < Nn) rowptr[i] = sm[threadIdx.x] - v;
    if (threadIdx.x == 255) bsum[blockIdx.x] = sm[255];
}

__global__ void scan3_kernel(int* __restrict__ rowptr, int* __restrict__ cursor,
                             const int* __restrict__ bsum, int Nn, int E) {
    __shared__ int sred[256];
    int t = threadIdx.x;
    int partial = 0;
    for (int j = t; j < blockIdx.x; j += 256) partial += bsum[j];
    sred[t] = partial;
    __syncthreads();
    for (int off = 128; off > 0; off >>= 1) {
        if (t < off) sred[t] += sred[t + off];
        __syncthreads();
    }
    int blockOff = sred[0];
    int i = blockIdx.x * 256 + t;
    if (i < Nn) {
        int v = rowptr[i] + blockOff;
        rowptr[i] = v;
        cursor[i] = v;
    }
    if (i == 0) rowptr[Nn] = E;
}

__global__ void fill_kernel(int* __restrict__ adj, int* __restrict__ cursor,
                            const int* __restrict__ ei, int E) {
    int e = blockIdx.x * blockDim.x + threadIdx.x;
    if (e < E) {
        int s = ei[e];
        int d = ei[(size_t)E + e];
        int p = atomicAdd(&cursor[d], 1);
        adj[p] = s;
    }
}

// ---------------------------------------------------------------------------
// tf32 helpers
// ---------------------------------------------------------------------------
__device__ __forceinline__ float totf(float x) {     // round fp32 -> tf32
    unsigned r;
    asm("cvt.rna.tf32.f32 %0, %1;" : "=r"(r) : "f"(x));
    return __uint_as_float(r);
}

__device__ __forceinline__ void mma_tf32(float d[4], const unsigned a[4],
                                         const unsigned b[2]) {
    asm volatile(
        "mma.sync.aligned.m16n8k8.row.col.f32.tf32.tf32.f32 "
        "{%0,%1,%2,%3}, {%4,%5,%6,%7}, {%8,%9}, {%0,%1,%2,%3};"
        : "+f"(d[0]), "+f"(d[1]), "+f"(d[2]), "+f"(d[3])
        : "r"(a[0]), "r"(a[1]), "r"(a[2]), "r"(a[3]), "r"(b[0]), "r"(b[1]));
}

// SMEM layout (floats):
//   X_hi [256 x 68], X_lo [256 x 68]  (gathered rows, tf32 hi/lo; reused for H1)
//   W1hi/W1lo/W2hi/W2lo [64 x 72]     ([k][n] row-major, stride 72)
#define XSTR 68
#define WSTR 72
#define XTILE (256 * XSTR)          // 17408
#define WTILE (64 * WSTR)           // 4608
#define OFF_XHI  0
#define OFF_XLO  XTILE
#define OFF_W1HI (2 * XTILE)
#define OFF_W1LO (2 * XTILE + WTILE)
#define OFF_W2HI (2 * XTILE + 2 * WTILE)
#define OFF_W2LO (2 * XTILE + 3 * WTILE)
#define LAYER_SMEM_BYTES ((2 * XTILE + 4 * WTILE) * 4)   // 212992

// 3-pass split GEMM: acc += X @ W over K=64, warp tile 2x2 of m16n8k8.
__device__ __forceinline__ void gemm_tf32(const float* __restrict__ sXhi,
                                          const float* __restrict__ sXlo,
                                          const float* __restrict__ sWhi,
                                          const float* __restrict__ sWlo,
                                          int m0, int n0, int lane,
                                          float acc[2][2][4]) {
    int qr = lane >> 2;   // 0..7
    int qc = lane & 3;    // 0..3
#pragma unroll
    for (int ks = 0; ks < 8; ks++) {
        int k0 = ks * 8;
        unsigned ahi[2][4], alo[2][4], bhi[2][2], blo[2][2];
#pragma unroll
        for (int rt = 0; rt < 2; rt++) {
            int row = m0 + rt * 16 + qr;
            const float* ph = sXhi + row * XSTR + k0 + qc;
            const float* pl = sXlo + row * XSTR + k0 + qc;
            ahi[rt][0] = __float_as_uint(ph[0]);
            ahi[rt][1] = __float_as_uint(ph[8 * XSTR]);
            ahi[rt][2] = __float_as_uint(ph[4]);
            ahi[rt][3] = __float_as_uint(ph[8 * XSTR + 4]);
            alo[rt][0] = __float_as_uint(pl[0]);
            alo[rt][1] = __float_as_uint(pl[8 * XSTR]);
            alo[rt][2] = __float_as_uint(pl[4]);
            alo[rt][3] = __float_as_uint(pl[8 * XSTR + 4]);
        }
#pragma unroll
        for (int ct = 0; ct < 2; ct++) {
            int n = n0 + ct * 8 + qr;
            const float* ph = sWhi + (k0 + qc) * WSTR + n;
            const float* pl = sWlo + (k0 + qc) * WSTR + n;
            bhi[ct][0] = __float_as_uint(ph[0]);
            bhi[ct][1] = __float_as_uint(ph[4 * WSTR]);
            blo[ct][0] = __float_as_uint(pl[0]);
            blo[ct][1] = __float_as_uint(pl[4 * WSTR]);
        }
#pragma unroll
        for (int rt = 0; rt < 2; rt++)
#pragma unroll
            for (int ct = 0; ct < 2; ct++) {
                mma_tf32(acc[rt][ct], ahi[rt], bhi[ct]);
                mma_tf32(acc[rt][ct], alo[rt], bhi[ct]);
                mma_tf32(acc[rt][ct], ahi[rt], blo[ct]);
            }
    }
}

// ---------------------------------------------------------------------------
// Fused GIN layer: Y = sigmoid(sigmoid((h + sum_neigh h) @ W1) @ W2)
//   1024 threads, 256 rows/block, 1 block/SM (208KB smem), 32 warps.
// ---------------------------------------------------------------------------
__global__ __launch_bounds__(1024, 1)
void layer_kernel(float* __restrict__ Y, const float* __restrict__ H,
                  const int* __restrict__ rowptr, const int* __restrict__ adj,
                  const float* __restrict__ W1, const float* __restrict__ W2,
                  float* __restrict__ xr, const int* __restrict__ batch, int Nn)
{
    extern __shared__ float smf[];
    int tid  = threadIdx.x;
    int lane = tid & 31;
    int row0 = blockIdx.x * 256;

    // ---- stage W1/W2 hi/lo ([k][n], stride 72) ----
#pragma unroll
    for (int it = 0; it < 4; it++) {
        int idx = tid + it * 1024;       // 0..4095
        int k = idx >> 6, n = idx & 63;
        int off = k * WSTR + n;
        float w1 = W1[idx], w2 = W2[idx];
        float h1 = totf(w1), h2 = totf(w2);
        smf[OFF_W1HI + off] = h1;
        smf[OFF_W1LO + off] = totf(w1 - h1);
        smf[OFF_W2HI + off] = h2;
        smf[OFF_W2LO + off] = totf(w2 - h2);
    }

    // ---- gather 256 rows (half-warp per node) -> X hi/lo tiles ----
    {
        int half = lane & 16;
        unsigned hmask = half ? 0xffff0000u : 0x0000ffffu;
        int t  = lane & 15;
        int hw = tid >> 4;               // 0..63
        const float4* H4 = (const float4*)H;
#pragma unroll
        for (int pass = 0; pass < 4; pass++) {
            int r = pass * 64 + hw;      // local row 0..255
            int n = row0 + r;
            int n_cl = (n < Nn) ? n : (Nn - 1);
            int start = rowptr[n_cl];
            int end   = rowptr[n_cl + 1];
            float4 acc = H4[(size_t)n_cl * 16 + t];
            int base = start;
            for (; base + 16 <= end; base += 16) {
                int idx = adj[base + t];
#pragma unroll
                for (int g = 0; g < 4; g++) {
                    float4 v[4];
#pragma unroll
                    for (int j = 0; j < 4; j++) {
                        int s = __shfl_sync(hmask, idx, half + g * 4 + j);
                        v[j] = H4[(size_t)s * 16 + t];
                    }
#pragma unroll
                    for (int j = 0; j < 4; j++) {
                        acc.x += v[j].x; acc.y += v[j].y;
                        acc.z += v[j].z; acc.w += v[j].w;
                    }
                }
            }
            int rem = end - base;
            if (rem > 0) {
                int idx = (t < rem) ? adj[base + t] : 0;
                for (int j = 0; j < rem; j++) {
                    int s = __shfl_sync(hmask, idx, half + j);
                    float4 v = H4[(size_t)s * 16 + t];
                    acc.x += v.x; acc.y += v.y; acc.z += v.z; acc.w += v.w;
                }
            }
            float4 hi4, lo4;
            hi4.x = totf(acc.x); lo4.x = totf(acc.x - hi4.x);
            hi4.y = totf(acc.y); lo4.y = totf(acc.y - hi4.y);
            hi4.z = totf(acc.z); lo4.z = totf(acc.z - hi4.z);
            hi4.w = totf(acc.w); lo4.w = totf(acc.w - hi4.w);
            *(float4*)(smf + OFF_XHI + r * XSTR + t * 4) = hi4;
            *(float4*)(smf + OFF_XLO + r * XSTR + t * 4) = lo4;
        }
    }
    __syncthreads();

    // warp tiling: colPair = w&3 (cols 16cp..16cp+15), rowPair = w>>2 (rows 32rp..32rp+31)
    int w  = tid >> 5;
    int n0 = (w & 3) * 16;
    int m0 = (w >> 2) * 32;
    int qr = lane >> 2, qc = lane & 3;

    float acc[2][2][4];

    // ---- GEMM1 + sigmoid -> H1 (back into X tiles) ----
#pragma unroll
    for (int rt = 0; rt < 2; rt++)
#pragma unroll
        for (int ct = 0; ct < 2; ct++)
#pragma unroll
            for (int i = 0; i < 4; i++) acc[rt][ct][i] = 0.0f;

    gemm_tf32(smf + OFF_XHI, smf + OFF_XLO, smf + OFF_W1HI, smf + OFF_W1LO,
              m0, n0, lane, acc);
    __syncthreads();                     // all GEMM1 reads of X done
#pragma unroll
    for (int rt = 0; rt < 2; rt++)
#pragma unroll
        for (int ct = 0; ct < 2; ct++) {
            int col = n0 + ct * 8 + 2 * qc;
#pragma unroll
            for (int hrow = 0; hrow < 2; hrow++) {
                int row = m0 + rt * 16 + qr + hrow * 8;
                float s0 = 1.0f / (1.0f + __expf(-acc[rt][ct][2 * hrow + 0]));
                float s1 = 1.0f / (1.0f + __expf(-acc[rt][ct][2 * hrow + 1]));
                float h0 = totf(s0), h1v = totf(s1);
                *(float2*)(smf + OFF_XHI + row * XSTR + col) = make_float2(h0, h1v);
                *(float2*)(smf + OFF_XLO + row * XSTR + col) =
                    make_float2(totf(s0 - h0), totf(s1 - h1v));
            }
        }
    __syncthreads();

    // ---- GEMM2 + sigmoid -> global (or RED into xr[batch]) ----
#pragma unroll
    for (int rt = 0; rt < 2; rt++)
#pragma unroll
        for (int ct = 0; ct < 2; ct++)
#pragma unroll
            for (int i = 0; i < 4; i++) acc[rt][ct][i] = 0.0f;

    gemm_tf32(smf + OFF_XHI, smf + OFF_XLO, smf + OFF_W2HI, smf + OFF_W2LO,
              m0, n0, lane, acc);

#pragma unroll
    for (int rt = 0; rt < 2; rt++)
#pragma unroll
        for (int ct = 0; ct < 2; ct++) {
            int col = n0 + ct * 8 + 2 * qc;
#pragma unroll
            for (int hrow = 0; hrow < 2; hrow++) {
                int row = row0 + m0 + rt * 16 + qr + hrow * 8;
                if (row < Nn) {
                    float s0 = 1.0f / (1.0f + __expf(-acc[rt][ct][2 * hrow + 0]));
                    float s1 = 1.0f / (1.0f + __expf(-acc[rt][ct][2 * hrow + 1]));
                    if (xr == nullptr) {
                        *(float2*)(Y + (size_t)row * 64 + col) = make_float2(s0, s1);
                    } else {
                        int g = batch[row];
                        float* p = xr + (size_t)g * 64 + col;
                        asm volatile("red.global.add.v2.f32 [%0], {%1, %2};"
                                     :: "l"(p), "f"(s0), "f"(s1) : "memory");
                    }
                }
            }
        }
}

// ---------------------------------------------------------------------------
// head: logits = xr @ fc_w^T + fc_b ; out = log_softmax(logits)
// ---------------------------------------------------------------------------
__global__ void head_kernel(float* __restrict__ out, const float* __restrict__ xr,
                            const float* __restrict__ fc_w, const float* __restrict__ fc_b,
                            int C, int B) {
    int g = blockIdx.x * blockDim.x + threadIdx.x;
    if (g >= B) return;
    float xv[FEAT];
#pragma unroll
    for (int i = 0; i < FEAT; i++) xv[i] = xr[(size_t)g * FEAT + i];
    float lg[16];
    float m = -1e30f;
    for (int c = 0; c < C; c++) {
        float s = fc_b[c];
#pragma unroll
        for (int i = 0; i < FEAT; i++) s += xv[i] * fc_w[(size_t)c * FEAT + i];
        lg[c] = s;
        m = fmaxf(m, s);
    }
    float sum = 0.0f;
    for (int c = 0; c < C; c++) sum += expf(lg[c] - m);
    float lse = m + logf(sum);
    for (int c = 0; c < C; c++) out[(size_t)g * C + c] = lg[c] - lse;
}

// ---------------------------------------------------------------------------
extern "C" void kernel_launch(void* const* d_in, const int* in_sizes, int n_in,
                              void* d_out, int out_size) {
    const float* x     = (const float*)d_in[0];
    const int*   ei    = (const int*)d_in[1];    // int64 narrowed to int32 by harness
    const int*   batch = (const int*)d_in[2];
    const float* W1s   = (const float*)d_in[3];
    const float* W2s   = (const float*)d_in[4];
    const float* fc_w  = (const float*)d_in[5];
    const float* fc_b  = (const float*)d_in[6];

    int Nn = in_sizes[0] / FEAT;           // 100000
    int E  = in_sizes[1] / 2;              // 1600000
    int C  = in_sizes[6];                  // 10
    int L  = in_sizes[3] / (FEAT * FEAT);  // 4
    int B  = out_size / (C + FEAT);        // 128

    static int smem_set = 0;
    if (!smem_set) {
        cudaFuncSetAttribute(layer_kernel,
                             cudaFuncAttributeMaxDynamicSharedMemorySize,
                             LAYER_SMEM_BYTES);
        smem_set = 1;
    }

    float4 *bufA4, *bufB4;
    int *rowptr, *cursor, *adj, *bsum;
    cudaGetSymbolAddress((void**)&bufA4, g_bufA);
    cudaGetSymbolAddress((void**)&bufB4, g_bufB);
    cudaGetSymbolAddress((void**)&rowptr, g_rowptr);
    cudaGetSymbolAddress((void**)&cursor, g_cursor);
    cudaGetSymbolAddress((void**)&adj, g_adj);
    cudaGetSymbolAddress((void**)&bsum, g_bsum);
    float* A  = (float*)bufA4;
    float* Bv = (float*)bufB4;

    int nb        = (Nn + 255) / 256;
    int eBlocks   = (E + 255) / 256;
    int layerBlks = (Nn + 255) / 256;

    float* out = (float*)d_out;
    float* xr  = out + (size_t)B * C;

    // ---- CSR build + output zeroing ----
    zero_both_kernel<<<nb, 256>>>(out, out_size, cursor, Nn);
    hist_kernel<<<eBlocks, 256>>>(cursor, ei, E);
    scan1_kernel<<<nb, 256>>>(cursor, rowptr, bsum, Nn);
    scan3_kernel<<<nb, 256>>>(rowptr, cursor, bsum, Nn, E);
    fill_kernel<<<eBlocks, 256>>>(adj, cursor, ei, E);

    // ---- layers (ping-pong; final layer REDs into xr instead of writing H) ----
    const float* H = x;
    float* Y = A;
    for (int l = 0; l < L; l++) {
        bool last = (l == L - 1);
        layer_kernel<<<layerBlks, 1024, LAYER_SMEM_BYTES>>>(
            Y, H, rowptr, adj,
            W1s + (size_t)l * FEAT * FEAT, W2s + (size_t)l * FEAT * FEAT,
            last ? xr : nullptr, batch, Nn);
        H = Y;
        Y = (Y == A) ? Bv : A;
    }

    head_kernel<<<(B + 127) / 128, 128>>>(out, xr, fc_w, fc_b, C, B);
}

// round 15
// speedup vs baseline: 1.2349x; 1.0400x over previous
#include <cuda_runtime.h>

#define FEAT 64

// Scratch buffers (static __device__ — no allocation allowed).
#define NMAX 100000
#define EMAX 1600000
__device__ float4 g_bufA[(size_t)NMAX * (FEAT / 4)];
__device__ float4 g_bufB[(size_t)NMAX * (FEAT / 4)];
__device__ int    g_rowptr[NMAX + 1];
__device__ int    g_cursor[NMAX];
__device__ int    g_adj[EMAX];
__device__ int    g_bsum[1024];

// ---------------------------------------------------------------------------
__global__ void zero_both_kernel(float* __restrict__ out, int nOut,
                                 int* __restrict__ cursor, int nInt) {
    int i = blockIdx.x * blockDim.x + threadIdx.x;
    if (i < nOut) out[i] = 0.0f;
    if (i < nInt) cursor[i] = 0;
}

// ---------------------------------------------------------------------------
// CSR build: histogram -> scan -> fill
// ---------------------------------------------------------------------------
__global__ void hist_kernel(int* __restrict__ deg, const int* __restrict__ ei, int E) {
    int e = blockIdx.x * blockDim.x + threadIdx.x;
    if (e < E) atomicAdd(&deg[ei[(size_t)E + e]], 1);
}

__global__ void scan1_kernel(const int* __restrict__ deg, int* __restrict__ rowptr,
                             int* __restrict__ bsum, int Nn) {
    __shared__ int sm[256];
    int i = blockIdx.x * 256 + threadIdx.x;
    int v = (i < Nn) ? deg[i] : 0;
    sm[threadIdx.x] = v;
    __syncthreads();
    for (int off = 1; off < 256; off <<= 1) {
        int t = (threadIdx.x >= off) ? sm[threadIdx.x - off] : 0;
        __syncthreads();
        sm[threadIdx.x] += t;
        __syncthreads();
    }
    if (i < Nn) rowptr[i] = sm[threadIdx.x] - v;
    if (threadIdx.x == 255) bsum[blockIdx.x] = sm[255];
}

__global__ void scan3_kernel(int* __restrict__ rowptr, int* __restrict__ cursor,
                             const int* __restrict__ bsum, int Nn, int E) {
    __shared__ int sred[256];
    int t = threadIdx.x;
    int partial = 0;
    for (int j = t; j < blockIdx.x; j += 256) partial += bsum[j];
    sred[t] = partial;
    __syncthreads();
    for (int off = 128; off > 0; off >>= 1) {
        if (t < off) sred[t] += sred[t + off];
        __syncthreads();
    }
    int blockOff = sred[0];
    int i = blockIdx.x * 256 + t;
    if (i < Nn) {
        int v = rowptr[i] + blockOff;
        rowptr[i] = v;
        cursor[i] = v;
    }
    if (i == 0) rowptr[Nn] = E;
}

__global__ void fill_kernel(int* __restrict__ adj, int* __restrict__ cursor,
                            const int* __restrict__ ei, int E) {
    int e = blockIdx.x * blockDim.x + threadIdx.x;
    if (e < E) {
        int s = ei[e];
        int d = ei[(size_t)E + e];
        int p = atomicAdd(&cursor[d], 1);
        adj[p] = s;
    }
}

// ---------------------------------------------------------------------------
// tf32 helpers
// ---------------------------------------------------------------------------
__device__ __forceinline__ float totf(float x) {     // round fp32 -> tf32
    unsigned r;
    asm("cvt.rna.tf32.f32 %0, %1;" : "=r"(r) : "f"(x));
    return __uint_as_float(r);
}

__device__ __forceinline__ void mma_tf32(float d[4], const unsigned a[4],
                                         const unsigned b[2]) {
    asm volatile(
        "mma.sync.aligned.m16n8k8.row.col.f32.tf32.tf32.f32 "
        "{%0,%1,%2,%3}, {%4,%5,%6,%7}, {%8,%9}, {%0,%1,%2,%3};"
        : "+f"(d[0]), "+f"(d[1]), "+f"(d[2]), "+f"(d[3])
        : "r"(a[0]), "r"(a[1]), "r"(a[2]), "r"(a[3]), "r"(b[0]), "r"(b[1]));
}

// SMEM (floats):
//   X_hi [128 x 68], X_lo [128 x 68]  (gathered rows; reused for H1)
//   W_hi [64 x 72],  W_lo [64 x 72]   (single W buffer, staged twice)
#define XSTR 68
#define WSTR 72
#define XTILE (128 * XSTR)          // 8704
#define WTILE (64 * WSTR)           // 4608
#define OFF_XHI  0
#define OFF_XLO  XTILE
#define OFF_WHI  (2 * XTILE)
#define OFF_WLO  (2 * XTILE + WTILE)
#define LAYER_SMEM_BYTES ((2 * XTILE + 2 * WTILE) * 4)   // 106496 -> 2 blocks/SM

__device__ __forceinline__ void stage_w(float* __restrict__ smf,
                                        const float* __restrict__ W, int tid) {
#pragma unroll
    for (int it = 0; it < 8; it++) {
        int idx = tid + it * 512;        // 0..4095
        int k = idx >> 6, n = idx & 63;
        int off = k * WSTR + n;
        float w = W[idx];
        float h = totf(w);
        smf[OFF_WHI + off] = h;
        smf[OFF_WLO + off] = totf(w - h);
    }
}

// 3-pass split GEMM: acc += X @ W over K=64, warp tile 2x2 of m16n8k8.
__device__ __forceinline__ void gemm_tf32(const float* __restrict__ sXhi,
                                          const float* __restrict__ sXlo,
                                          const float* __restrict__ sWhi,
                                          const float* __restrict__ sWlo,
                                          int m0, int n0, int lane,
                                          float acc[2][2][4]) {
    int qr = lane >> 2;   // 0..7
    int qc = lane & 3;    // 0..3
#pragma unroll
    for (int ks = 0; ks < 8; ks++) {
        int k0 = ks * 8;
        unsigned ahi[2][4], alo[2][4], bhi[2][2], blo[2][2];
#pragma unroll
        for (int rt = 0; rt < 2; rt++) {
            int row = m0 + rt * 16 + qr;
            const float* ph = sXhi + row * XSTR + k0 + qc;
            const float* pl = sXlo + row * XSTR + k0 + qc;
            ahi[rt][0] = __float_as_uint(ph[0]);
            ahi[rt][1] = __float_as_uint(ph[8 * XSTR]);
            ahi[rt][2] = __float_as_uint(ph[4]);
            ahi[rt][3] = __float_as_uint(ph[8 * XSTR + 4]);
            alo[rt][0] = __float_as_uint(pl[0]);
            alo[rt][1] = __float_as_uint(pl[8 * XSTR]);
            alo[rt][2] = __float_as_uint(pl[4]);
            alo[rt][3] = __float_as_uint(pl[8 * XSTR + 4]);
        }
#pragma unroll
        for (int ct = 0; ct < 2; ct++) {
            int n = n0 + ct * 8 + qr;
            const float* ph = sWhi + (k0 + qc) * WSTR + n;
            const float* pl = sWlo + (k0 + qc) * WSTR + n;
            bhi[ct][0] = __float_as_uint(ph[0]);
            bhi[ct][1] = __float_as_uint(ph[4 * WSTR]);
            blo[ct][0] = __float_as_uint(pl[0]);
            blo[ct][1] = __float_as_uint(pl[4 * WSTR]);
        }
#pragma unroll
        for (int rt = 0; rt < 2; rt++)
#pragma unroll
            for (int ct = 0; ct < 2; ct++) {
                mma_tf32(acc[rt][ct], ahi[rt], bhi[ct]);
                mma_tf32(acc[rt][ct], alo[rt], bhi[ct]);
                mma_tf32(acc[rt][ct], ahi[rt], blo[ct]);
            }
    }
}

// ---------------------------------------------------------------------------
// Fused GIN layer: Y = sigmoid(sigmoid((h + sum_neigh h) @ W1) @ W2)
//   512 threads, 128 rows/block, 2 blocks/SM -> gather/GEMM phases of the
//   two resident blocks overlap (L2 vs tensor pipes).
// ---------------------------------------------------------------------------
__global__ __launch_bounds__(512, 2)
void layer_kernel(float* __restrict__ Y, const float* __restrict__ H,
                  const int* __restrict__ rowptr, const int* __restrict__ adj,
                  const float* __restrict__ W1, const float* __restrict__ W2,
                  float* __restrict__ xr, const int* __restrict__ batch, int Nn)
{
    extern __shared__ float smf[];
    int tid  = threadIdx.x;
    int lane = tid & 31;
    int row0 = blockIdx.x * 128;

    // ---- stage W1 hi/lo ----
    stage_w(smf, W1, tid);

    // ---- gather 128 rows (half-warp per node) -> X hi/lo tiles ----
    {
        int half = lane & 16;
        unsigned hmask = half ? 0xffff0000u : 0x0000ffffu;
        int t  = lane & 15;
        int hw = tid >> 4;               // 0..31
        const float4* H4 = (const float4*)H;
#pragma unroll
        for (int pass = 0; pass < 4; pass++) {
            int r = pass * 32 + hw;      // local row 0..127
            int n = row0 + r;
            int n_cl = (n < Nn) ? n : (Nn - 1);
            int start = rowptr[n_cl];
            int end   = rowptr[n_cl + 1];
            float4 acc = H4[(size_t)n_cl * 16 + t];
            int base = start;
            for (; base + 16 <= end; base += 16) {
                int idx = adj[base + t];
#pragma unroll
                for (int g = 0; g < 4; g++) {
                    float4 v[4];
#pragma unroll
                    for (int j = 0; j < 4; j++) {
                        int s = __shfl_sync(hmask, idx, half + g * 4 + j);
                        v[j] = H4[(size_t)s * 16 + t];
                    }
#pragma unroll
                    for (int j = 0; j < 4; j++) {
                        acc.x += v[j].x; acc.y += v[j].y;
                        acc.z += v[j].z; acc.w += v[j].w;
                    }
                }
            }
            int rem = end - base;
            if (rem > 0) {
                int idx = (t < rem) ? adj[base + t] : 0;
                for (int j = 0; j < rem; j++) {
                    int s = __shfl_sync(hmask, idx, half + j);
                    float4 v = H4[(size_t)s * 16 + t];
                    acc.x += v.x; acc.y += v.y; acc.z += v.z; acc.w += v.w;
                }
            }
            float4 hi4, lo4;
            hi4.x = totf(acc.x); lo4.x = totf(acc.x - hi4.x);
            hi4.y = totf(acc.y); lo4.y = totf(acc.y - hi4.y);
            hi4.z = totf(acc.z); lo4.z = totf(acc.z - hi4.z);
            hi4.w = totf(acc.w); lo4.w = totf(acc.w - hi4.w);
            *(float4*)(smf + OFF_XHI + r * XSTR + t * 4) = hi4;
            *(float4*)(smf + OFF_XLO + r * XSTR + t * 4) = lo4;
        }
    }
    __syncthreads();

    // warp tiling (16 warps): rows (w>>2)*32, cols (w&3)*16
    int w  = tid >> 5;
    int n0 = (w & 3) * 16;
    int m0 = (w >> 2) * 32;
    int qr = lane >> 2, qc = lane & 3;

    float acc[2][2][4];

    // ---- GEMM1 ----
#pragma unroll
    for (int rt = 0; rt < 2; rt++)
#pragma unroll
        for (int ct = 0; ct < 2; ct++)
#pragma unroll
            for (int i = 0; i < 4; i++) acc[rt][ct][i] = 0.0f;

    gemm_tf32(smf + OFF_XHI, smf + OFF_XLO, smf + OFF_WHI, smf + OFF_WLO,
              m0, n0, lane, acc);
    __syncthreads();                     // all reads of X and W1 done

    // ---- H1 writeback (into X tiles) + stage W2 (overlapped) ----
#pragma unroll
    for (int rt = 0; rt < 2; rt++)
#pragma unroll
        for (int ct = 0; ct < 2; ct++) {
            int col = n0 + ct * 8 + 2 * qc;
#pragma unroll
            for (int hrow = 0; hrow < 2; hrow++) {
                int row = m0 + rt * 16 + qr + hrow * 8;
                float s0 = 1.0f / (1.0f + __expf(-acc[rt][ct][2 * hrow + 0]));
                float s1 = 1.0f / (1.0f + __expf(-acc[rt][ct][2 * hrow + 1]));
                float h0 = totf(s0), h1v = totf(s1);
                *(float2*)(smf + OFF_XHI + row * XSTR + col) = make_float2(h0, h1v);
                *(float2*)(smf + OFF_XLO + row * XSTR + col) =
                    make_float2(totf(s0 - h0), totf(s1 - h1v));
            }
        }
    stage_w(smf, W2, tid);
    __syncthreads();

    // ---- GEMM2 + sigmoid -> global (or RED into xr[batch]) ----
#pragma unroll
    for (int rt = 0; rt < 2; rt++)
#pragma unroll
        for (int ct = 0; ct < 2; ct++)
#pragma unroll
            for (int i = 0; i < 4; i++) acc[rt][ct][i] = 0.0f;

    gemm_tf32(smf + OFF_XHI, smf + OFF_XLO, smf + OFF_WHI, smf + OFF_WLO,
              m0, n0, lane, acc);

#pragma unroll
    for (int rt = 0; rt < 2; rt++)
#pragma unroll
        for (int ct = 0; ct < 2; ct++) {
            int col = n0 + ct * 8 + 2 * qc;
#pragma unroll
            for (int hrow = 0; hrow < 2; hrow++) {
                int row = row0 + m0 + rt * 16 + qr + hrow * 8;
                if (row < Nn) {
                    float s0 = 1.0f / (1.0f + __expf(-acc[rt][ct][2 * hrow + 0]));
                    float s1 = 1.0f / (1.0f + __expf(-acc[rt][ct][2 * hrow + 1]));
                    if (xr == nullptr) {
                        *(float2*)(Y + (size_t)row * 64 + col) = make_float2(s0, s1);
                    } else {
                        int g = batch[row];
                        float* p = xr + (size_t)g * 64 + col;
                        asm volatile("red.global.add.v2.f32 [%0], {%1, %2};"
                                     :: "l"(p), "f"(s0), "f"(s1) : "memory");
                    }
                }
            }
        }
}

// ---------------------------------------------------------------------------
// head: logits = xr @ fc_w^T + fc_b ; out = log_softmax(logits)
// ---------------------------------------------------------------------------
__global__ void head_kernel(float* __restrict__ out, const float* __restrict__ xr,
                            const float* __restrict__ fc_w, const float* __restrict__ fc_b,
                            int C, int B) {
    int g = blockIdx.x * blockDim.x + threadIdx.x;
    if (g >= B) return;
    float xv[FEAT];
#pragma unroll
    for (int i = 0; i < FEAT; i++) xv[i] = xr[(size_t)g * FEAT + i];
    float lg[16];
    float m = -1e30f;
    for (int c = 0; c < C; c++) {
        float s = fc_b[c];
#pragma unroll
        for (int i = 0; i < FEAT; i++) s += xv[i] * fc_w[(size_t)c * FEAT + i];
        lg[c] = s;
        m = fmaxf(m, s);
    }
    float sum = 0.0f;
    for (int c = 0; c < C; c++) sum += expf(lg[c] - m);
    float lse = m + logf(sum);
    for (int c = 0; c < C; c++) out[(size_t)g * C + c] = lg[c] - lse;
}

// ---------------------------------------------------------------------------
extern "C" void kernel_launch(void* const* d_in, const int* in_sizes, int n_in,
                              void* d_out, int out_size) {
    const float* x     = (const float*)d_in[0];
    const int*   ei    = (const int*)d_in[1];    // int64 narrowed to int32 by harness
    const int*   batch = (const int*)d_in[2];
    const float* W1s   = (const float*)d_in[3];
    const float* W2s   = (const float*)d_in[4];
    const float* fc_w  = (const float*)d_in[5];
    const float* fc_b  = (const float*)d_in[6];

    int Nn = in_sizes[0] / FEAT;           // 100000
    int E  = in_sizes[1] / 2;              // 1600000
    int C  = in_sizes[6];                  // 10
    int L  = in_sizes[3] / (FEAT * FEAT);  // 4
    int B  = out_size / (C + FEAT);        // 128

    static int smem_set = 0;
    if (!smem_set) {
        cudaFuncSetAttribute(layer_kernel,
                             cudaFuncAttributeMaxDynamicSharedMemorySize,
                             LAYER_SMEM_BYTES);
        smem_set = 1;
    }

    float4 *bufA4, *bufB4;
    int *rowptr, *cursor, *adj, *bsum;
    cudaGetSymbolAddress((void**)&bufA4, g_bufA);
    cudaGetSymbolAddress((void**)&bufB4, g_bufB);
    cudaGetSymbolAddress((void**)&rowptr, g_rowptr);
    cudaGetSymbolAddress((void**)&cursor, g_cursor);
    cudaGetSymbolAddress((void**)&adj, g_adj);
    cudaGetSymbolAddress((void**)&bsum, g_bsum);
    float* A  = (float*)bufA4;
    float* Bv = (float*)bufB4;

    int nb        = (Nn + 255) / 256;
    int eBlocks   = (E + 255) / 256;
    int layerBlks = (Nn + 127) / 128;

    float* out = (float*)d_out;
    float* xr  = out + (size_t)B * C;

    // ---- CSR build + output zeroing ----
    zero_both_kernel<<<nb, 256>>>(out, out_size, cursor, Nn);
    hist_kernel<<<eBlocks, 256>>>(cursor, ei, E);
    scan1_kernel<<<nb, 256>>>(cursor, rowptr, bsum, Nn);
    scan3_kernel<<<nb, 256>>>(rowptr, cursor, bsum, Nn, E);
    fill_kernel<<<eBlocks, 256>>>(adj, cursor, ei, E);

    // ---- layers (ping-pong; final layer REDs into xr instead of writing H) ----
    const float* H = x;
    float* Y = A;
    for (int l = 0; l < L; l++) {
        bool last = (l == L - 1);
        layer_kernel<<<layerBlks, 512, LAYER_SMEM_BYTES>>>(
            Y, H, rowptr, adj,
            W1s + (size_t)l * FEAT * FEAT, W2s + (size_t)l * FEAT * FEAT,
            last ? xr : nullptr, batch, Nn);
        H = Y;
        Y = (Y == A) ? Bv : A;
    }

    head_kernel<<<(B + 127) / 128, 128>>>(out, xr, fc_w, fc_b, C, B);
}